// round 4
// baseline (speedup 1.0000x reference)
#include <cuda_runtime.h>
#include <math.h>

// Problem constants
#define T_TOK   2048
#define D_MODEL 1024
#define D_FF    4096
#define N_EXP   24
#define N_PAIR  (T_TOK*2)

// GEMM tile config (tensor-core version)
#define BM 64
#define BN 128
#define BK 16

// -------------------- device scratch ----------------------------------------
__device__ int   g_cnt[N_EXP];
__device__ int   g_off[N_EXP];
__device__ int   g_tok_e[N_PAIR];
__device__ float g_tok_w[N_PAIR];
__device__ int   g_pair_pos[N_PAIR];
__device__ float g_xg[(size_t)N_PAIR * D_MODEL];
__device__ float g_h [(size_t)N_PAIR * D_FF];
__device__ float g_y [(size_t)N_PAIR * D_MODEL];

// -------------------- small kernels (unchanged) ------------------------------
__global__ void moe_zero() {
    int i = threadIdx.x;
    if (i < N_EXP) g_cnt[i] = 0;
}

__global__ void moe_gate(const float* __restrict__ x,
                         const float* __restrict__ gw,
                         const float* __restrict__ gb) {
    int t = blockIdx.x;
    __shared__ float xs[D_MODEL];
    __shared__ float part[N_EXP][4];
    __shared__ float scores[N_EXP];

    for (int d = threadIdx.x; d < D_MODEL; d += blockDim.x)
        xs[d] = x[(size_t)t * D_MODEL + d];
    __syncthreads();

    int tid = threadIdx.x;
    if (tid < 96) {
        int e = tid % N_EXP;
        int q = tid / N_EXP;
        float s = 0.f;
        int d0 = q * 256;
        for (int d = d0; d < d0 + 256; ++d)
            s += xs[d] * gw[d * N_EXP + e];
        part[e][q] = s;
    }
    __syncthreads();
    if (tid < N_EXP)
        scores[tid] = part[tid][0] + part[tid][1] + part[tid][2] + part[tid][3] + gb[tid];
    __syncthreads();

    if (tid == 0) {
        int i0 = 0; float v0 = scores[0];
        for (int e = 1; e < N_EXP; ++e) if (scores[e] > v0) { v0 = scores[e]; i0 = e; }
        int i1 = -1; float v1 = -3.0e38f;
        for (int e = 0; e < N_EXP; ++e) if (e != i0 && scores[e] > v1) { v1 = scores[e]; i1 = e; }
        float g0 = 1.f / (1.f + expf(v1 - v0));
        float g1 = 1.f - g0;

        int p0 = atomicAdd(&g_cnt[i0], 1);
        int p1 = atomicAdd(&g_cnt[i1], 1);
        g_tok_e[2*t]     = i0;  g_tok_e[2*t+1]     = i1;
        g_tok_w[2*t]     = g0;  g_tok_w[2*t+1]     = g1;
        g_pair_pos[2*t]  = p0;  g_pair_pos[2*t+1]  = p1;
    }
}

__global__ void moe_prefix() {
    if (threadIdx.x == 0) {
        int a = 0;
        for (int e = 0; e < N_EXP; ++e) { g_off[e] = a; a += g_cnt[e]; }
    }
}

__global__ void moe_gather(const float* __restrict__ x) {
    int id = blockIdx.x;
    int t  = id >> 1;
    int e  = g_tok_e[id];
    int pair = g_off[e] + g_pair_pos[id];
    const float4* src = (const float4*)(x + (size_t)t * D_MODEL);
    float4* dst = (float4*)(g_xg + (size_t)pair * D_MODEL);
    dst[threadIdx.x] = src[threadIdx.x];
}

// -------------------- tf32 tensor-core GEMM ----------------------------------
__device__ __forceinline__ unsigned f2tf(float f) {
    unsigned u; asm("cvt.rna.tf32.f32 %0, %1;" : "=r"(u) : "f"(f)); return u;
}

__device__ __forceinline__ void mma_tf32(float* c, const unsigned* a, const unsigned* b) {
    asm volatile(
        "mma.sync.aligned.m16n8k8.row.col.f32.tf32.tf32.f32 "
        "{%0,%1,%2,%3}, {%4,%5,%6,%7}, {%8,%9}, {%0,%1,%2,%3};"
        : "+f"(c[0]), "+f"(c[1]), "+f"(c[2]), "+f"(c[3])
        : "r"(a[0]), "r"(a[1]), "r"(a[2]), "r"(a[3]), "r"(b[0]), "r"(b[1]));
}

// C[M,ND] = (GELU?) ( A[M,KD] @ W_e[KD,ND] + b_e )
// A = g_xg (GELU path) or g_h ; C = g_h or g_y
template<int KD, int ND, bool GELU>
__global__ void __launch_bounds__(256)
moe_gemm_tc(const float* __restrict__ Wbase, const float* __restrict__ Bbase) {
    int e   = blockIdx.z;
    int cnt = g_cnt[e];
    int m0  = blockIdx.y * BM;
    if (m0 >= cnt) return;
    int off = g_off[e];
    int n0  = blockIdx.x * BN;

    const float* A = (GELU ? g_xg : g_h) + (size_t)off * KD;
    const float* W = Wbase + (size_t)e * KD * ND;
    float*       C = (GELU ? g_h  : g_y);

    // As: [m][k] stride 20 (bank-conflict-free frag LDS + aligned STS.128)
    // Bs: [k][n] stride 132
    __shared__ float As[2][BM][BK + 4];
    __shared__ float Bs[2][BK][BN + 4];

    int tid  = threadIdx.x;
    int lane = tid & 31;
    int wid  = tid >> 5;          // 0..7
    int wm   = wid & 1;           // 2 warps along M (32 rows each)
    int wn   = wid >> 1;          // 4 warps along N (32 cols each)
    int g    = lane >> 2;         // 0..7
    int tg   = lane & 3;          // 0..3

    // global-load assignments
    int ar = tid >> 2;            // 0..63  (A row)
    int ac = (tid & 3) * 4;       // 0,4,8,12 (A k)
    int br = tid >> 5;            // 0..7   (B k rows br, br+8)
    int bc = (tid & 31) * 4;      // 0..124 (B n)

    int arow = min(m0 + ar, cnt - 1);
    const float* Aptr = A + (size_t)arow * KD + ac;
    const float* Wptr = W + (size_t)br * ND + n0 + bc;

    float acc[2][4][4] = {};

    // ---- preload tile 0 ----
    float4 av  = *(const float4*)(Aptr);
    float4 bv0 = *(const float4*)(Wptr);
    float4 bv1 = *(const float4*)(Wptr + (size_t)8 * ND);
    {
        float* as = &As[0][ar][ac];
        as[0] = __uint_as_float(f2tf(av.x));
        as[1] = __uint_as_float(f2tf(av.y));
        as[2] = __uint_as_float(f2tf(av.z));
        as[3] = __uint_as_float(f2tf(av.w));
        float4 c0 = make_float4(__uint_as_float(f2tf(bv0.x)), __uint_as_float(f2tf(bv0.y)),
                                __uint_as_float(f2tf(bv0.z)), __uint_as_float(f2tf(bv0.w)));
        float4 c1 = make_float4(__uint_as_float(f2tf(bv1.x)), __uint_as_float(f2tf(bv1.y)),
                                __uint_as_float(f2tf(bv1.z)), __uint_as_float(f2tf(bv1.w)));
        *(float4*)&Bs[0][br][bc]     = c0;
        *(float4*)&Bs[0][br + 8][bc] = c1;
    }
    __syncthreads();

    const int NIT = KD / BK;
    int buf = 0;

    #pragma unroll 1
    for (int it = 0; it < NIT; ++it) {
        // prefetch next tile into registers
        bool more = (it + 1 < NIT);
        if (more) {
            int k0 = (it + 1) * BK;
            av  = *(const float4*)(Aptr + k0);
            const float* wp = Wptr + (size_t)k0 * ND;
            bv0 = *(const float4*)wp;
            bv1 = *(const float4*)(wp + (size_t)8 * ND);
        }

        // ---- compute on current buffer ----
        {
            const float (*as)[BK + 4] = As[buf];
            const float (*bs)[BN + 4] = Bs[buf];
            #pragma unroll
            for (int ks = 0; ks < 2; ++ks) {
                int k0 = ks * 8;
                unsigned a[2][4], b[4][2];
                #pragma unroll
                for (int mi = 0; mi < 2; ++mi) {
                    int m = wm * 32 + mi * 16;
                    a[mi][0] = __float_as_uint(as[m + g    ][k0 + tg]);
                    a[mi][1] = __float_as_uint(as[m + g + 8][k0 + tg]);
                    a[mi][2] = __float_as_uint(as[m + g    ][k0 + tg + 4]);
                    a[mi][3] = __float_as_uint(as[m + g + 8][k0 + tg + 4]);
                }
                #pragma unroll
                for (int ni = 0; ni < 4; ++ni) {
                    int n = wn * 32 + ni * 8;
                    b[ni][0] = __float_as_uint(bs[k0 + tg    ][n + g]);
                    b[ni][1] = __float_as_uint(bs[k0 + tg + 4][n + g]);
                }
                #pragma unroll
                for (int mi = 0; mi < 2; ++mi)
                    #pragma unroll
                    for (int ni = 0; ni < 4; ++ni)
                        mma_tf32(acc[mi][ni], a[mi], b[ni]);
            }
        }

        // ---- stage next tile into other buffer ----
        if (more) {
            int nb = buf ^ 1;
            float* as = &As[nb][ar][ac];
            as[0] = __uint_as_float(f2tf(av.x));
            as[1] = __uint_as_float(f2tf(av.y));
            as[2] = __uint_as_float(f2tf(av.z));
            as[3] = __uint_as_float(f2tf(av.w));
            float4 c0 = make_float4(__uint_as_float(f2tf(bv0.x)), __uint_as_float(f2tf(bv0.y)),
                                    __uint_as_float(f2tf(bv0.z)), __uint_as_float(f2tf(bv0.w)));
            float4 c1 = make_float4(__uint_as_float(f2tf(bv1.x)), __uint_as_float(f2tf(bv1.y)),
                                    __uint_as_float(f2tf(bv1.z)), __uint_as_float(f2tf(bv1.w)));
            *(float4*)&Bs[nb][br][bc]     = c0;
            *(float4*)&Bs[nb][br + 8][bc] = c1;
            __syncthreads();
            buf = nb;
        }
    }

    // ---- epilogue ----
    #pragma unroll
    for (int mi = 0; mi < 2; ++mi) {
        #pragma unroll
        for (int ni = 0; ni < 4; ++ni) {
            int nc = n0 + wn * 32 + ni * 8 + 2 * tg;
            float bb0 = Bbase[e * ND + nc];
            float bb1 = Bbase[e * ND + nc + 1];
            #pragma unroll
            for (int h = 0; h < 2; ++h) {
                int m = m0 + wm * 32 + mi * 16 + g + 8 * h;
                if (m >= cnt) continue;
                float v0 = acc[mi][ni][2 * h]     + bb0;
                float v1 = acc[mi][ni][2 * h + 1] + bb1;
                if (GELU) {
                    v0 = 0.5f * v0 * (1.f + erff(v0 * 0.70710678118654752f));
                    v1 = 0.5f * v1 * (1.f + erff(v1 * 0.70710678118654752f));
                }
                float2 r = make_float2(v0, v1);
                *(float2*)(C + (size_t)(off + m) * ND + nc) = r;
            }
        }
    }
}

// -------------------- combine ------------------------------------------------
__global__ void moe_combine(const float* __restrict__ x, float* __restrict__ out) {
    int t = blockIdx.x;
    int e0 = g_tok_e[2*t], e1 = g_tok_e[2*t+1];
    float w0 = g_tok_w[2*t], w1 = g_tok_w[2*t+1];
    size_t p0 = (size_t)(g_off[e0] + g_pair_pos[2*t])   * D_MODEL;
    size_t p1 = (size_t)(g_off[e1] + g_pair_pos[2*t+1]) * D_MODEL;

    int i = threadIdx.x;
    const float4* xv = (const float4*)(x + (size_t)t * D_MODEL);
    const float4* y0 = (const float4*)(g_y + p0);
    const float4* y1 = (const float4*)(g_y + p1);
    float4 a = xv[i], c0 = y0[i], c1 = y1[i];
    float4 r;
    r.x = a.x + w0 * c0.x + w1 * c1.x;
    r.y = a.y + w0 * c0.y + w1 * c1.y;
    r.z = a.z + w0 * c0.z + w1 * c1.z;
    r.w = a.w + w0 * c0.w + w1 * c1.w;
    ((float4*)(out + (size_t)t * D_MODEL))[i] = r;
}

// -------------------- launch -------------------------------------------------
extern "C" void kernel_launch(void* const* d_in, const int* in_sizes, int n_in,
                              void* d_out, int out_size) {
    const float* x  = (const float*)d_in[0];
    const float* gw = (const float*)d_in[1];
    const float* gb = (const float*)d_in[2];
    const float* w1 = (const float*)d_in[3];
    const float* b1 = (const float*)d_in[4];
    const float* w2 = (const float*)d_in[5];
    const float* b2 = (const float*)d_in[6];
    float* out = (float*)d_out;

    moe_zero<<<1, 32>>>();
    moe_gate<<<T_TOK, 128>>>(x, gw, gb);
    moe_prefix<<<1, 1>>>();
    moe_gather<<<N_PAIR, 256>>>(x);

    moe_gemm_tc<D_MODEL, D_FF, true>
        <<<dim3(D_FF / BN, T_TOK / BM, N_EXP), 256>>>(w1, b1);
    moe_gemm_tc<D_FF, D_MODEL, false>
        <<<dim3(D_MODEL / BN, T_TOK / BM, N_EXP), 256>>>(w2, b2);

    moe_combine<<<T_TOK, 256>>>(x, out);
}

// round 6
// speedup vs baseline: 3.2997x; 3.2997x over previous
#include <cuda_runtime.h>
#include <cuda_bf16.h>
#include <math.h>
#include <stdint.h>

#define T_TOK   2048
#define D_MODEL 1024
#define D_FF    4096
#define N_EXP   24
#define N_PAIR  (T_TOK*2)
#define PAD_ROWS 256

// ---------------- device scratch ----------------
__device__ int   g_cnt[N_EXP];
__device__ int   g_off[N_EXP];
__device__ int   g_tok_e[N_PAIR];
__device__ float g_tok_w[N_PAIR];
__device__ int   g_pair_pos[N_PAIR];
__device__ __nv_bfloat16 g_xg[(size_t)(N_PAIR + PAD_ROWS) * D_MODEL];
__device__ __nv_bfloat16 g_h [(size_t)(N_PAIR + PAD_ROWS) * D_FF];
__device__ float         g_y [(size_t)(N_PAIR + PAD_ROWS) * D_MODEL];

// ---------------- helpers ----------------
__device__ __forceinline__ uint32_t smem_u32(const void* p) {
    uint32_t a;
    asm("{ .reg .u64 t; cvta.to.shared.u64 t, %1; cvt.u32.u64 %0, t; }" : "=r"(a) : "l"(p));
    return a;
}
__device__ __forceinline__ uint32_t pk(float lo, float hi) {   // bf16x2: lo at low half
    uint32_t r; asm("cvt.rn.bf16x2.f32 %0, %1, %2;" : "=r"(r) : "f"(hi), "f"(lo)); return r;
}
__device__ __forceinline__ void cp16(uint32_t sa, const void* g) {
    asm volatile("cp.async.cg.shared.global [%0], [%1], 16;" :: "r"(sa), "l"(g) : "memory");
}
#define CP_COMMIT() asm volatile("cp.async.commit_group;" ::: "memory")
#define CP_WAIT0()  asm volatile("cp.async.wait_group 0;" ::: "memory")

__device__ __forceinline__ void ldsm4(uint32_t* r, uint32_t a) {
    asm volatile("ldmatrix.sync.aligned.m8n8.x4.shared.b16 {%0,%1,%2,%3}, [%4];"
        : "=r"(r[0]), "=r"(r[1]), "=r"(r[2]), "=r"(r[3]) : "r"(a));
}
__device__ __forceinline__ void ldsm4t(uint32_t* r, uint32_t a) {
    asm volatile("ldmatrix.sync.aligned.m8n8.x4.trans.shared.b16 {%0,%1,%2,%3}, [%4];"
        : "=r"(r[0]), "=r"(r[1]), "=r"(r[2]), "=r"(r[3]) : "r"(a));
}
__device__ __forceinline__ void mma_bf16(float* c, const uint32_t* a, uint32_t b0, uint32_t b1) {
    asm volatile(
        "mma.sync.aligned.m16n8k16.row.col.f32.bf16.bf16.f32 "
        "{%0,%1,%2,%3}, {%4,%5,%6,%7}, {%8,%9}, {%0,%1,%2,%3};"
        : "+f"(c[0]), "+f"(c[1]), "+f"(c[2]), "+f"(c[3])
        : "r"(a[0]), "r"(a[1]), "r"(a[2]), "r"(a[3]), "r"(b0), "r"(b1));
}

// ---------------- small kernels ----------------
__global__ void moe_zero() { if (threadIdx.x < N_EXP) g_cnt[threadIdx.x] = 0; }

__global__ void moe_gate(const float* __restrict__ x, const float* __restrict__ gw,
                         const float* __restrict__ gb) {
    int t = blockIdx.x;
    __shared__ float xs[D_MODEL];
    __shared__ float part[N_EXP][4];
    __shared__ float scores[N_EXP];
    for (int d = threadIdx.x; d < D_MODEL; d += blockDim.x)
        xs[d] = x[(size_t)t * D_MODEL + d];
    __syncthreads();
    int tid = threadIdx.x;
    if (tid < 96) {
        int e = tid % N_EXP, q = tid / N_EXP;
        float s = 0.f;
        for (int d = q * 256; d < q * 256 + 256; ++d) s += xs[d] * gw[d * N_EXP + e];
        part[e][q] = s;
    }
    __syncthreads();
    if (tid < N_EXP)
        scores[tid] = part[tid][0] + part[tid][1] + part[tid][2] + part[tid][3] + gb[tid];
    __syncthreads();
    if (tid == 0) {
        int i0 = 0; float v0 = scores[0];
        for (int e = 1; e < N_EXP; ++e) if (scores[e] > v0) { v0 = scores[e]; i0 = e; }
        int i1 = -1; float v1 = -3.0e38f;
        for (int e = 0; e < N_EXP; ++e) if (e != i0 && scores[e] > v1) { v1 = scores[e]; i1 = e; }
        float g0 = 1.f / (1.f + expf(v1 - v0));
        int p0 = atomicAdd(&g_cnt[i0], 1);
        int p1 = atomicAdd(&g_cnt[i1], 1);
        g_tok_e[2*t] = i0; g_tok_e[2*t+1] = i1;
        g_tok_w[2*t] = g0; g_tok_w[2*t+1] = 1.f - g0;
        g_pair_pos[2*t] = p0; g_pair_pos[2*t+1] = p1;
    }
}

__global__ void moe_prefix() {
    if (threadIdx.x == 0) {
        int a = 0;
        for (int e = 0; e < N_EXP; ++e) { g_off[e] = a; a += g_cnt[e]; }
    }
}

__global__ void moe_gather(const float* __restrict__ x) {
    int id = blockIdx.x;
    int t = id >> 1;
    int pair = g_off[g_tok_e[id]] + g_pair_pos[id];
    float4 v = ((const float4*)(x + (size_t)t * D_MODEL))[threadIdx.x];
    uint2 o; o.x = pk(v.x, v.y); o.y = pk(v.z, v.w);
    ((uint2*)(g_xg + (size_t)pair * D_MODEL))[threadIdx.x] = o;
}

// ---------------- bf16 mma.sync GEMM ----------------
// C[M,ND] = (GELU?)(A[M,KD](bf16) @ W_e[KD,ND](fp32->bf16) + b_e)
// BM=128 BN=128 BK=32, 256 threads, 8 warps as 2(m) x 4(n).
template<int KD, int ND, bool GELU>
__global__ void __launch_bounds__(256)
moe_mm(const float* __restrict__ W_all, const float* __restrict__ B_all) {
    __shared__ __align__(128) uint8_t As[2][8192];   // 128 rows x 32 bf16, swizzled
    __shared__ __align__(128) uint8_t Bs[2][8192];   // 32 rows x 128 bf16, swizzled
    __shared__ float bias_s[128];

    const int e = blockIdx.z, cnt = g_cnt[e];
    const int m0 = blockIdx.y * 128;
    if (m0 >= cnt) return;
    const int off = g_off[e];
    const int n0 = blockIdx.x * 128;

    const __nv_bfloat16* A = (GELU ? g_xg : g_h) + (size_t)(off + m0) * KD;
    const float* W = W_all + (size_t)e * KD * ND + n0;

    const int tid = threadIdx.x, lane = tid & 31, wid = tid >> 5;
    const int wm = wid >> 2, wn = wid & 3;          // 2 x 4 warp grid
    const int l15 = lane & 15, lh = lane >> 4;

    if (tid < 128) bias_s[tid] = B_all[e * ND + n0 + tid];

    const uint32_t asb[2] = { smem_u32(As[0]), smem_u32(As[1]) };

    // A staging: 2 x 16B per thread
    uint32_t asw[2]; int agoff[2];
    #pragma unroll
    for (int j = 0; j < 2; ++j) {
        int idx = tid + 256 * j, ar = idx >> 2, ac = idx & 3;
        asw[j]   = (uint32_t)(ar * 64 + ((ac ^ ((ar >> 1) & 3)) * 16));
        agoff[j] = ar * KD + ac * 8;
    }
    // W staging: 4 x float4 per thread -> 4 x 8B bf16 STS
    uint32_t bswz[4]; size_t wgoff[4];
    #pragma unroll
    for (int j = 0; j < 4; ++j) {
        int idx = tid + 256 * j, wk = idx >> 5, wng = idx & 31;
        bswz[j]  = (uint32_t)(wk * 256 + (((wng >> 1) ^ (wk & 7)) * 16) + (wng & 1) * 8);
        wgoff[j] = (size_t)wk * ND + wng * 4;
    }

    float acc[4][4][4] = {};
    float4 wv[4];

    // ---- preload tile 0 ----
    #pragma unroll
    for (int j = 0; j < 2; ++j) cp16(asb[0] + asw[j], A + agoff[j]);
    CP_COMMIT();
    #pragma unroll
    for (int j = 0; j < 4; ++j) wv[j] = *(const float4*)(W + wgoff[j]);
    #pragma unroll
    for (int j = 0; j < 4; ++j) {
        uint2 o; o.x = pk(wv[j].x, wv[j].y); o.y = pk(wv[j].z, wv[j].w);
        *(uint2*)(Bs[0] + bswz[j]) = o;
    }
    CP_WAIT0();
    __syncthreads();

    const int NIT = KD / 32;
    #pragma unroll 1
    for (int it = 0; it < NIT; ++it) {
        const int buf = it & 1;
        const bool more = (it + 1) < NIT;
        if (more) {
            const int kk = (it + 1) * 32;
            #pragma unroll
            for (int j = 0; j < 2; ++j)
                cp16(asb[buf ^ 1] + asw[j], A + agoff[j] + kk);
            CP_COMMIT();
            #pragma unroll
            for (int j = 0; j < 4; ++j)
                wv[j] = *(const float4*)(W + (size_t)kk * ND + wgoff[j]);
        }
        // ---- compute current buffer ----
        const uint32_t ab = asb[buf];
        const uint32_t bb = smem_u32(Bs[buf]);
        #pragma unroll
        for (int ks = 0; ks < 2; ++ks) {
            uint32_t af[4][4], bfr[2][4];
            #pragma unroll
            for (int mi = 0; mi < 4; ++mi) {
                int mrow = wm * 64 + mi * 16 + l15;
                uint32_t cc = (uint32_t)((ks * 2 + lh) ^ ((mrow >> 1) & 3));
                ldsm4(af[mi], ab + mrow * 64 + cc * 16);
            }
            int r = ks * 16 + l15;
            #pragma unroll
            for (int p = 0; p < 2; ++p) {
                uint32_t chunk = (uint32_t)((wn * 4 + p * 2 + lh) ^ (r & 7));
                ldsm4t(bfr[p], bb + r * 256 + chunk * 16);
            }
            #pragma unroll
            for (int mi = 0; mi < 4; ++mi)
                #pragma unroll
                for (int ni = 0; ni < 4; ++ni)
                    mma_bf16(acc[mi][ni], af[mi],
                             bfr[ni >> 1][(ni & 1) * 2], bfr[ni >> 1][(ni & 1) * 2 + 1]);
        }
        if (more) {
            #pragma unroll
            for (int j = 0; j < 4; ++j) {
                uint2 o; o.x = pk(wv[j].x, wv[j].y); o.y = pk(wv[j].z, wv[j].w);
                *(uint2*)(Bs[buf ^ 1] + bswz[j]) = o;
            }
            CP_WAIT0();
            __syncthreads();
        }
    }

    // ---- epilogue ----
    const int rbase = wm * 64 + (lane >> 2);
    #pragma unroll
    for (int mi = 0; mi < 4; ++mi) {
        #pragma unroll
        for (int ni = 0; ni < 4; ++ni) {
            int col = wn * 32 + ni * 8 + (lane & 3) * 2;
            float b0 = bias_s[col], b1 = bias_s[col + 1];
            #pragma unroll
            for (int h = 0; h < 2; ++h) {
                int r = rbase + mi * 16 + 8 * h;
                if (r >= cnt - m0) continue;
                float v0 = acc[mi][ni][2 * h]     + b0;
                float v1 = acc[mi][ni][2 * h + 1] + b1;
                size_t cix = (size_t)(off + m0 + r) * ND + n0 + col;
                if (GELU) {
                    v0 = 0.5f * v0 * (1.f + erff(v0 * 0.70710678118654752f));
                    v1 = 0.5f * v1 * (1.f + erff(v1 * 0.70710678118654752f));
                    *(uint32_t*)(g_h + cix) = pk(v0, v1);
                } else {
                    float2 o = make_float2(v0, v1);
                    *(float2*)(g_y + cix) = o;
                }
            }
        }
    }
}

// ---------------- combine ----------------
__global__ void moe_combine(const float* __restrict__ x, float* __restrict__ out) {
    int t = blockIdx.x;
    float w0 = g_tok_w[2*t], w1 = g_tok_w[2*t+1];
    size_t p0 = (size_t)(g_off[g_tok_e[2*t]]   + g_pair_pos[2*t])   * D_MODEL;
    size_t p1 = (size_t)(g_off[g_tok_e[2*t+1]] + g_pair_pos[2*t+1]) * D_MODEL;
    int i = threadIdx.x;
    float4 a  = ((const float4*)(x + (size_t)t * D_MODEL))[i];
    float4 c0 = ((const float4*)(g_y + p0))[i];
    float4 c1 = ((const float4*)(g_y + p1))[i];
    float4 r;
    r.x = a.x + w0*c0.x + w1*c1.x;  r.y = a.y + w0*c0.y + w1*c1.y;
    r.z = a.z + w0*c0.z + w1*c1.z;  r.w = a.w + w0*c0.w + w1*c1.w;
    ((float4*)(out + (size_t)t * D_MODEL))[i] = r;
}

// ---------------- launch ----------------
extern "C" void kernel_launch(void* const* d_in, const int* in_sizes, int n_in,
                              void* d_out, int out_size) {
    const float* x  = (const float*)d_in[0];
    const float* gw = (const float*)d_in[1];
    const float* gb = (const float*)d_in[2];
    const float* w1 = (const float*)d_in[3];
    const float* b1 = (const float*)d_in[4];
    const float* w2 = (const float*)d_in[5];
    const float* b2 = (const float*)d_in[6];
    float* out = (float*)d_out;

    moe_zero<<<1, 32>>>();
    moe_gate<<<T_TOK, 128>>>(x, gw, gb);
    moe_prefix<<<1, 1>>>();
    moe_gather<<<N_PAIR, 256>>>(x);

    moe_mm<D_MODEL, D_FF, true>
        <<<dim3(D_FF / 128, T_TOK / 128, N_EXP), 256>>>(w1, b1);
    moe_mm<D_FF, D_MODEL, false>
        <<<dim3(D_MODEL / 128, T_TOK / 128, N_EXP), 256>>>(w2, b2);

    moe_combine<<<T_TOK, 256>>>(x, out);
}